// round 1
// baseline (speedup 1.0000x reference)
#include <cuda_runtime.h>
#include <cuda_fp16.h>
#include <cstdint>

// Problem dims (fixed by the dataset): x (4,2048,4096) fp32, qweight (4096,2048) int32
// (each int32 holds one packed byte = two 4-bit values, low nibble first),
// scale/zero (4096,32) fp32. out (4,2048,4096) fp32.
#define MDIM 8192
#define NDIM 4096
#define KDIM 4096
#define GROUPS 32  // KDIM / 128

// Scratch (allocation-free rule: __device__ globals)
__device__ __align__(16) __half g_xh[(size_t)MDIM * KDIM];  // 64 MB
__device__ __align__(16) __half g_wh[(size_t)NDIM * KDIM];  // 32 MB

// ---------------------------------------------------------------------------
// Prep kernel 1: x fp32 -> fp16 (vectorized float4 -> 8B)
// ---------------------------------------------------------------------------
__global__ void xconv_kernel(const float* __restrict__ x) {
    int i = blockIdx.x * blockDim.x + threadIdx.x;  // one float4 per thread
    float4 v = reinterpret_cast<const float4*>(x)[i];
    union { uint2 u; __half2 h[2]; } pk;
    pk.h[0] = __floats2half2_rn(v.x, v.y);
    pk.h[1] = __floats2half2_rn(v.z, v.w);
    reinterpret_cast<uint2*>(g_xh)[i] = pk.u;
}

// ---------------------------------------------------------------------------
// Prep kernel 2: int4 group-dequant -> fp16 weights
// Each thread: 4 packed int32 (= 8 weights, all in the same group) -> uint4 store
// ---------------------------------------------------------------------------
__global__ void dequant_kernel(const int* __restrict__ qw,
                               const float* __restrict__ scale,
                               const float* __restrict__ zero) {
    int i = blockIdx.x * blockDim.x + threadIdx.x;  // int4 index
    int4 q = reinterpret_cast<const int4*>(qw)[i];
    int o  = i >> 9;        // 512 int4 per output row (2048 int32 / 4)
    int j4 = i & 511;
    int g  = (j4 * 8) >> 7; // group of the 8 unpacked positions (always uniform)
    float s = scale[o * GROUPS + g];
    float z = zero [o * GROUPS + g];
    int v[4] = {q.x, q.y, q.z, q.w};
    union { uint4 u; __half2 h[4]; } pk;
#pragma unroll
    for (int t = 0; t < 4; ++t) {
        float lo = (float)( v[t]       & 0xF);
        float hi = (float)((v[t] >> 4) & 0xF);
        pk.h[t] = __floats2half2_rn((lo - z) * s, (hi - z) * s);
    }
    reinterpret_cast<uint4*>(g_wh)[i] = pk.u;
}

// ---------------------------------------------------------------------------
// fp16 GEMM: out[M,N] = Xh[M,K] * Wh[N,K]^T, fp32 accumulate
// CTA tile 128x128x64, 8 warps (4x2), warp tile 32x64, mma.m16n8k16
// SW128-swizzled smem (128B rows), cp.async double buffer
// ---------------------------------------------------------------------------
#define BM 128
#define BN 128
#define BK 64
#define NKITER (KDIM / BK)

__device__ __forceinline__ void cp16(uint32_t s, const void* g) {
    asm volatile("cp.async.cg.shared.global [%0], [%1], 16;" :: "r"(s), "l"(g));
}
__device__ __forceinline__ void ldsm4(uint32_t& r0, uint32_t& r1, uint32_t& r2,
                                      uint32_t& r3, const __half* p) {
    uint32_t s = (uint32_t)__cvta_generic_to_shared(p);
    asm volatile("ldmatrix.sync.aligned.m8n8.x4.shared.b16 {%0,%1,%2,%3}, [%4];"
                 : "=r"(r0), "=r"(r1), "=r"(r2), "=r"(r3) : "r"(s));
}
__device__ __forceinline__ void mma16816(float* d, const uint32_t* a, const uint32_t* b) {
    asm volatile(
        "mma.sync.aligned.m16n8k16.row.col.f32.f16.f16.f32 "
        "{%0,%1,%2,%3}, {%4,%5,%6,%7}, {%8,%9}, {%0,%1,%2,%3};"
        : "+f"(d[0]), "+f"(d[1]), "+f"(d[2]), "+f"(d[3])
        : "r"(a[0]), "r"(a[1]), "r"(a[2]), "r"(a[3]), "r"(b[0]), "r"(b[1]));
}

__global__ void __launch_bounds__(256, 2) gemm_kernel(float* __restrict__ out) {
    extern __shared__ __half smem[];
    __half* sA = smem;                 // [2][BM*BK]
    __half* sB = smem + 2 * BM * BK;   // [2][BN*BK]

    const int tid  = threadIdx.x;
    const int warp = tid >> 5;
    const int lane = tid & 31;
    const int wm = warp >> 1;   // 0..3 (m)
    const int wn = warp & 1;    // 0..1 (n)
    const int m0 = blockIdx.y * BM;
    const int n0 = blockIdx.x * BN;

    const __half* gA = g_xh + (size_t)m0 * KDIM;
    const __half* gB = g_wh + (size_t)n0 * KDIM;

    const int ldRow = tid >> 3;  // 0..31
    const int ldCh  = tid & 7;   // 0..7 (16B chunk within 128B row)

    float acc[2][8][4];
#pragma unroll
    for (int mt = 0; mt < 2; ++mt)
#pragma unroll
        for (int nt = 0; nt < 8; ++nt)
#pragma unroll
            for (int r = 0; r < 4; ++r) acc[mt][nt][r] = 0.0f;

    // --- stage loader (SW128 swizzle: chunk ^= row&7) ---
    auto stage = [&](int buf, int k0) {
        uint32_t sAb = (uint32_t)__cvta_generic_to_shared(sA + buf * BM * BK);
        uint32_t sBb = (uint32_t)__cvta_generic_to_shared(sB + buf * BM * BK);
#pragma unroll
        for (int p = 0; p < 4; ++p) {
            int r  = ldRow + p * 32;
            int sw = (ldCh ^ (r & 7)) * 8;
            cp16(sAb + (uint32_t)(r * BK + sw) * 2, gA + (size_t)r * KDIM + k0 + ldCh * 8);
            cp16(sBb + (uint32_t)(r * BK + sw) * 2, gB + (size_t)r * KDIM + k0 + ldCh * 8);
        }
    };

    stage(0, 0);
    asm volatile("cp.async.commit_group;");

    for (int kt = 0; kt < NKITER; ++kt) {
        const int buf = kt & 1;
        if (kt + 1 < NKITER) {
            stage((kt + 1) & 1, (kt + 1) * BK);
            asm volatile("cp.async.commit_group;");
            asm volatile("cp.async.wait_group 1;");
        } else {
            asm volatile("cp.async.wait_group 0;");
        }
        __syncthreads();

        const __half* bufA = sA + buf * BM * BK;
        const __half* bufB = sB + buf * BM * BK;

#pragma unroll
        for (int ks = 0; ks < BK / 16; ++ks) {
            uint32_t aF[2][4];
#pragma unroll
            for (int mt = 0; mt < 2; ++mt) {
                int r  = wm * 32 + mt * 16 + (lane & 15);
                int ch = ks * 2 + (lane >> 4);
                const __half* p = bufA + r * BK + ((ch ^ (lane & 7)) * 8);
                ldsm4(aF[mt][0], aF[mt][1], aF[mt][2], aF[mt][3], p);
            }
            uint32_t bF[8][2];
#pragma unroll
            for (int nt2 = 0; nt2 < 4; ++nt2) {
                int r  = wn * 64 + nt2 * 16 + (lane & 7) + ((lane >> 4) << 3);
                int ch = ks * 2 + ((lane >> 3) & 1);
                const __half* p = bufB + r * BK + ((ch ^ (lane & 7)) * 8);
                uint32_t r0, r1, r2, r3;
                ldsm4(r0, r1, r2, r3, p);
                bF[nt2 * 2 + 0][0] = r0; bF[nt2 * 2 + 0][1] = r1;
                bF[nt2 * 2 + 1][0] = r2; bF[nt2 * 2 + 1][1] = r3;
            }
#pragma unroll
            for (int mt = 0; mt < 2; ++mt)
#pragma unroll
                for (int nt = 0; nt < 8; ++nt)
                    mma16816(acc[mt][nt], aF[mt], bF[nt]);
        }
        __syncthreads();
    }

    // --- epilogue: fp32 direct stores (8B per store, coalesced in quads) ---
    const int g  = lane >> 2;
    const int tg = lane & 3;
#pragma unroll
    for (int mt = 0; mt < 2; ++mt) {
        int row0 = m0 + wm * 32 + mt * 16;
#pragma unroll
        for (int nt = 0; nt < 8; ++nt) {
            int col = n0 + wn * 64 + nt * 8 + tg * 2;
            *reinterpret_cast<float2*>(out + (size_t)(row0 + g) * NDIM + col) =
                make_float2(acc[mt][nt][0], acc[mt][nt][1]);
            *reinterpret_cast<float2*>(out + (size_t)(row0 + g + 8) * NDIM + col) =
                make_float2(acc[mt][nt][2], acc[mt][nt][3]);
        }
    }
}

// ---------------------------------------------------------------------------
extern "C" void kernel_launch(void* const* d_in, const int* in_sizes, int n_in,
                              void* d_out, int out_size) {
    const float* x     = (const float*)d_in[0];
    const int*   qw    = (const int*)  d_in[1];
    const float* scale = (const float*)d_in[2];
    const float* zero  = (const float*)d_in[3];
    float* out = (float*)d_out;

    // prep: x -> fp16, W -> fp16 (independent, serialized on default stream)
    xconv_kernel<<<(MDIM * KDIM / 4) / 256, 256>>>(x);
    dequant_kernel<<<(NDIM * KDIM / 8) / 256, 256>>>(qw, scale, zero);

    // GEMM
    const int smem_bytes = 2 * (BM * BK + BN * BK) * (int)sizeof(__half);  // 64 KB
    cudaFuncSetAttribute(gemm_kernel, cudaFuncAttributeMaxDynamicSharedMemorySize,
                         smem_bytes);
    dim3 grid(NDIM / BN, MDIM / BM);
    gemm_kernel<<<grid, 256, smem_bytes>>>(out);
}